// round 2
// baseline (speedup 1.0000x reference)
#include <cuda_runtime.h>

#define NEG_INF __int_as_float(0xff800000)

#define XS 34              // smem img row stride (floats)
#define CSTRIDE (6*XS)     // 204 floats per channel tile (6 rows)

// Block: 128 threads = 32 x-lanes x 4 o-pair groups.
// Thread computes 2 o-channels (obase+g, obase+g+4) x 4 rows = 8 outputs.
// Grid: (oquarter=4, ytile=8, b=8) = 256 blocks -> all 148 SMs busy, 1 wave.
__global__ __launch_bounds__(128, 4)
void bconv_kernel(const float* __restrict__ img,
                  const float* __restrict__ ker,
                  float* __restrict__ out)
{
    __shared__ float simg[32 * CSTRIDE];   // 26112 B: 32 c x 6 rows x 34 cols (-inf pad)
    __shared__ float sker[32 * 72];        // 9216 B: 8-o slice, [c][p][g][j]

    const int oq  = blockIdx.x;            // 0..3
    const int yt  = blockIdx.y;            // 0..7
    const int b   = blockIdx.z;            // 0..7
    const int tid = threadIdx.x;
    const int x   = tid & 31;
    const int g   = tid >> 5;              // 0..3 (== warp id -> kv loads warp-uniform)
    const int y0  = yt * 4;
    const int obase = oq * 8;

    // ---- fill image tile: rows y0-1..y0+4, cols -1..32, -inf OOB ----
    const float* gimg = img + b * 32 * 32 * 32;
    for (int idx = tid; idx < 32 * CSTRIDE; idx += 128) {
        int c   = idx / CSTRIDE;
        int rem = idx - c * CSTRIDE;
        int r   = rem / XS;
        int xx  = rem - r * XS;
        int h   = y0 - 1 + r;
        int w   = xx - 1;
        float v = NEG_INF;
        if ((unsigned)h < 32u && (unsigned)w < 32u)
            v = gimg[(c * 32 + h) * 32 + w];
        simg[idx] = v;
    }

    // ---- fill flipped-kernel slice: sker[c*72 + p*8 + g*2 + j] = ker[obase+g+4j][c][2-dy][2-dx] ----
    for (int idx = tid; idx < 32 * 72; idx += 128) {
        int c   = idx / 72;
        int rem = idx - c * 72;
        int p   = rem >> 3;
        int gl  = (rem >> 1) & 3;
        int j   = rem & 1;
        int o   = obase + gl + 4 * j;
        int dy  = p / 3, dx = p - dy * 3;
        sker[idx] = ker[((o * 32 + c) * 3 + (2 - dy)) * 3 + (2 - dx)];
    }
    __syncthreads();

    float acc0[4], acc1[4];
#pragma unroll
    for (int i = 0; i < 4; i++) { acc0[i] = NEG_INF; acc1[i] = NEG_INF; }

    const float2* sk2 = (const float2*)sker;   // index: c*36 + p*4 + g (warp-uniform -> bcast)

    // double-buffered channel loop: load c+1 while computing c
    float vA[6][3], vB[6][3];
    float2 kA[9], kB[9];

#define LOADCH(VV, KK, c)                                        \
    do {                                                          \
        const float* ip = simg + (c) * CSTRIDE + x;               \
        _Pragma("unroll")                                         \
        for (int p = 0; p < 9; p++) KK[p] = sk2[(c)*36 + p*4 + g];\
        _Pragma("unroll")                                         \
        for (int r = 0; r < 6; r++) {                             \
            _Pragma("unroll")                                     \
            for (int d = 0; d < 3; d++) VV[r][d] = ip[r*XS + d];  \
        }                                                         \
    } while (0)

#define COMPCH(VV, KK)                                            \
    do {                                                          \
        _Pragma("unroll")                                         \
        for (int yy = 0; yy < 4; yy++) {                          \
            _Pragma("unroll")                                     \
            for (int dy = 0; dy < 3; dy++) {                      \
                _Pragma("unroll")                                 \
                for (int dx = 0; dx < 3; dx++) {                  \
                    float vv = VV[yy + dy][dx];                   \
                    float2 k = KK[dy*3 + dx];                     \
                    acc0[yy] = fmaxf(acc0[yy], vv + k.x);         \
                    acc1[yy] = fmaxf(acc1[yy], vv + k.y);         \
                }                                                 \
            }                                                     \
        }                                                         \
    } while (0)

    LOADCH(vA, kA, 0);
#pragma unroll 1
    for (int c = 0; c < 32; c += 2) {
        LOADCH(vB, kB, c + 1);        // loads for c+1 issue under compute of c
        COMPCH(vA, kA);
        int cn = (c + 2 < 32) ? (c + 2) : 0;   // harmless redundant load on last iter
        LOADCH(vA, kA, cn);
        COMPCH(vB, kB);
    }

    // ---- store: o = obase+g (acc0), obase+g+4 (acc1) ----
    float* gout = out + ((b * 32 + obase + g) * 32 + y0) * 32 + x;
#pragma unroll
    for (int yy = 0; yy < 4; yy++) gout[yy * 32] = acc0[yy];
    gout += 4 * 32 * 32;
#pragma unroll
    for (int yy = 0; yy < 4; yy++) gout[yy * 32] = acc1[yy];
}

extern "C" void kernel_launch(void* const* d_in, const int* in_sizes, int n_in,
                              void* d_out, int out_size)
{
    const float* img = (const float*)d_in[0];
    const float* ker = (const float*)d_in[1];
    float*       out = (float*)d_out;
    dim3 grid(4, 8, 8);   // (o-quarter, ytile, batch)
    bconv_kernel<<<grid, 128>>>(img, ker, out);
}